// round 5
// baseline (speedup 1.0000x reference)
#include <cuda_runtime.h>
#include <math.h>

// Row-invariant pooled-noise term: (noise[2j] + noise[2j+1]) * STD/2.
// 200 KB -> stays L2-resident across all 512 row-CTAs.
#define MAX_POOL 65536
__device__ float g_npool[MAX_POOL];

__global__ void npool_kernel(const float* __restrict__ noise, int halfL) {
    int j = blockIdx.x * blockDim.x + threadIdx.x;
    if (j < halfL) {
        // STD = 0.04, MEAN = 0.0; pooled pair contribution = (n0+n1)*0.5*STD
        g_npool[j] = (noise[2 * j] + noise[2 * j + 1]) * (0.5f * 0.04f);
    }
}

// One CTA per row. Phase A: stream row from DRAM, build pooled row in SMEM,
// accumulate sum/sumsq. Block reduce -> mu, 1/sd. Phase B: write normalized
// float2 pairs. Exactly one DRAM read + one DRAM write of the 205 MB tensor.
__global__ __launch_bounds__(1024, 1)
void fused_kernel(const float* __restrict__ x,
                  const int*   __restrict__ move_p,
                  float*       __restrict__ out,
                  int L) {
    extern __shared__ float s_pool[];          // halfL floats + 66 reduction slots
    const int halfL = L >> 1;
    float* s_red = s_pool + halfL;

    const int row = blockIdx.x;
    const float* __restrict__ xrow = x + (size_t)row * (size_t)L;
    float*       __restrict__ orow = out + (size_t)row * (size_t)L;

    int mv = __ldg(move_p);
    mv %= L; if (mv < 0) mv += L;

    float sum = 0.0f, sumsq = 0.0f;

    // ---- Phase A: pooled values into SMEM, partial moments in registers ----
    #pragma unroll 4
    for (int j = threadIdx.x; j < halfL; j += blockDim.x) {
        int s = 2 * j - mv;                    // (2j - move) mod L, one add fixes range
        if (s < 0) s += L;
        float a, b;
        if (((s & 1) == 0) && (s + 1 < L)) {   // warp-uniform except the wrap thread
            float2 v = *reinterpret_cast<const float2*>(xrow + s);
            a = v.x; b = v.y;
        } else {
            int s1 = s + 1; if (s1 >= L) s1 -= L;
            a = xrow[s]; b = xrow[s1];
        }
        float p = (a + b) * 0.5f + g_npool[j];
        s_pool[j] = p;
        sum   += p;
        sumsq += p * p;
    }

    // ---- Block reduction of (sum, sumsq) ----
    #pragma unroll
    for (int o = 16; o > 0; o >>= 1) {
        sum   += __shfl_down_sync(0xFFFFFFFFu, sum,   o);
        sumsq += __shfl_down_sync(0xFFFFFFFFu, sumsq, o);
    }
    const int wid  = threadIdx.x >> 5;
    const int lane = threadIdx.x & 31;
    const int nwarps = blockDim.x >> 5;
    if (lane == 0) { s_red[wid] = sum; s_red[32 + wid] = sumsq; }
    __syncthreads();
    if (threadIdx.x < 32) {
        float s2 = (threadIdx.x < nwarps) ? s_red[threadIdx.x]      : 0.0f;
        float q2 = (threadIdx.x < nwarps) ? s_red[32 + threadIdx.x] : 0.0f;
        #pragma unroll
        for (int o = 16; o > 0; o >>= 1) {
            s2 += __shfl_down_sync(0xFFFFFFFFu, s2, o);
            q2 += __shfl_down_sync(0xFFFFFFFFu, q2, o);
        }
        if (threadIdx.x == 0) {
            float inv_n = 1.0f / (float)halfL;
            float mu    = s2 * inv_n;
            float var   = fmaxf(q2 * inv_n - mu * mu, 0.0f);
            s_red[64] = mu;
            s_red[65] = rsqrtf(var);
        }
    }
    __syncthreads();
    const float mu     = s_red[64];
    const float inv_sd = s_red[65];

    // ---- Phase B: normalized duplicated writes, float2-coalesced ----
    #pragma unroll 4
    for (int j = threadIdx.x; j < halfL; j += blockDim.x) {
        float v = (s_pool[j] - mu) * inv_sd;
        float2 w; w.x = v; w.y = v;
        *reinterpret_cast<float2*>(orow + 2 * j) = w;
    }
}

extern "C" void kernel_launch(void* const* d_in, const int* in_sizes, int n_in,
                              void* d_out, int out_size) {
    const float* x     = (const float*)d_in[0];
    const float* noise = (const float*)d_in[1];
    const int*   move  = (const int*)d_in[2];
    float*       out   = (float*)d_out;

    const int L     = in_sizes[1];          // 100000
    const int B     = in_sizes[0] / L;      // 512
    const int halfL = L / 2;                // 50000

    npool_kernel<<<(halfL + 255) / 256, 256>>>(noise, halfL);

    size_t smem = (size_t)halfL * sizeof(float) + 66 * sizeof(float);
    cudaFuncSetAttribute(fused_kernel,
                         cudaFuncAttributeMaxDynamicSharedMemorySize,
                         (int)smem);
    fused_kernel<<<B, 1024, smem>>>(x, move, out, L);
}